// round 6
// baseline (speedup 1.0000x reference)
#include <cuda_runtime.h>
#include <cstdint>

#define Bq    128
#define NTREE 2047
#define DIN   512
#define NLS   64
#define MROWS (Bq * NTREE)
#define NKT   (DIN / 32)

// Scratch (no allocations allowed): emissions + ping-pong inside buffers.
__device__ float g_emis[(size_t)MROWS * NLS];        // 67 MB
__device__ float g_bufA[(size_t)Bq * 512 * NLS];     // 16.8 MB
__device__ float g_bufB[(size_t)Bq * 512 * NLS];     // 16.8 MB

// tf32 MMA reads only the tf32 bit-fields of the operand register; feeding raw
// fp32 bits == RZ truncation (error budget: ~3e-5 final rel err, gate is 1e-3).
__device__ __forceinline__ uint32_t f2tf32(float f) { return __float_as_uint(f); }

__device__ __forceinline__ void mma_tf32(float c[4], const uint32_t a[4], const uint32_t b[2]) {
    asm volatile(
        "mma.sync.aligned.m16n8k8.row.col.f32.tf32.tf32.f32 "
        "{%0,%1,%2,%3}, {%4,%5,%6,%7}, {%8,%9}, {%0,%1,%2,%3};"
        : "+f"(c[0]), "+f"(c[1]), "+f"(c[2]), "+f"(c[3])
        : "r"(a[0]), "r"(a[1]), "r"(a[2]), "r"(a[3]), "r"(b[0]), "r"(b[1]));
}

__device__ __forceinline__ void cp_async16(void* smem_dst, const void* gmem_src) {
    uint32_t dst = (uint32_t)__cvta_generic_to_shared(smem_dst);
    asm volatile("cp.async.cg.shared.global [%0], [%1], 16;"
                 :: "r"(dst), "l"(gmem_src) : "memory");
}
__device__ __forceinline__ void cp_commit() {
    asm volatile("cp.async.commit_group;" ::: "memory");
}
__device__ __forceinline__ void cp_wait1() {
    asm volatile("cp.async.wait_group 1;" ::: "memory");
}

// ---------------------------------------------------------------------------
// Emission GEMM: emis[M,64] = hidden[M,512] @ W[512,64] + b
// BM=128, BN=64, BK=32; 256 threads = 8 warps in 4(M) x 2(N); warp tile 32x32.
// 3-stage cp.async pipeline, dynamic smem (81 KB) -> 2 CTAs/SM.
// ---------------------------------------------------------------------------
#define AS_STRIDE 36
#define BS_STRIDE 72
#define A_STAGE   (128 * AS_STRIDE)
#define B_STAGE   (32 * BS_STRIDE)
#define EMIS_SMEM ((3 * A_STAGE + 3 * B_STAGE) * 4)   // 82944 bytes

extern __shared__ float dynsm[];

__global__ __launch_bounds__(256) void emis_kernel(
    const float* __restrict__ hidden, const float* __restrict__ W,
    const float* __restrict__ bias, float* __restrict__ emis)
{
    const int t    = threadIdx.x;
    const int wid  = t >> 5, lane = t & 31;
    const int g    = lane >> 2, tig = lane & 3;
    const int wm   = wid & 3, wn = wid >> 2;
    const size_t brow = (size_t)blockIdx.x * 128;

    float* Abase = dynsm;
    float* Bbase = dynsm + 3 * A_STAGE;

    const int a_r0 = t >> 3, a_c4 = t & 7;    // A: rows a_r0 + 32*i
    const int b_r0 = t >> 4, b_c4 = t & 15;   // B: rows b_r0 + 16*i

    auto load_tiles = [&](int kt, int s) {
        const int kb = kt * 32;
        float* As = Abase + s * A_STAGE;
        float* Bs = Bbase + s * B_STAGE;
        #pragma unroll
        for (int i = 0; i < 4; i++) {
            int r = a_r0 + 32 * i;
            cp_async16(As + r * AS_STRIDE + a_c4 * 4,
                       hidden + (brow + r) * DIN + kb + a_c4 * 4);
        }
        #pragma unroll
        for (int i = 0; i < 2; i++) {
            int r = b_r0 + 16 * i;
            cp_async16(Bs + r * BS_STRIDE + b_c4 * 4,
                       W + (size_t)(kb + r) * NLS + b_c4 * 4);
        }
        cp_commit();
    };

    float acc[2][4][4];
    #pragma unroll
    for (int mi = 0; mi < 2; mi++)
        #pragma unroll
        for (int ni = 0; ni < 4; ni++)
            #pragma unroll
            for (int j = 0; j < 4; j++) acc[mi][ni][j] = 0.f;

    load_tiles(0, 0);
    load_tiles(1, 1);

    for (int kt = 0; kt < NKT; kt++) {
        cp_wait1();
        __syncthreads();
        // Always commit a group: keeps wait_group accounting exact so that at
        // the final iterations the newest (possibly pending) group is empty
        // and the data group for this stage is guaranteed complete.
        if (kt + 2 < NKT) load_tiles(kt + 2, (kt + 2) % 3);
        else              cp_commit();

        const int s = kt % 3;
        const float* As = Abase + s * A_STAGE;
        const float* Bs = Bbase + s * B_STAGE;

        #pragma unroll
        for (int kk = 0; kk < 4; kk++) {
            const int k0 = kk * 8;
            uint32_t a[2][4];
            #pragma unroll
            for (int mi = 0; mi < 2; mi++) {
                int r0 = wm * 32 + mi * 16;
                a[mi][0] = f2tf32(As[(r0 + g) * AS_STRIDE + k0 + tig]);
                a[mi][1] = f2tf32(As[(r0 + 8 + g) * AS_STRIDE + k0 + tig]);
                a[mi][2] = f2tf32(As[(r0 + g) * AS_STRIDE + k0 + tig + 4]);
                a[mi][3] = f2tf32(As[(r0 + 8 + g) * AS_STRIDE + k0 + tig + 4]);
            }
            uint32_t bf[4][2];
            #pragma unroll
            for (int ni = 0; ni < 4; ni++) {
                int c0 = wn * 32 + ni * 8;
                bf[ni][0] = f2tf32(Bs[(k0 + tig) * BS_STRIDE + c0 + g]);
                bf[ni][1] = f2tf32(Bs[(k0 + tig + 4) * BS_STRIDE + c0 + g]);
            }
            #pragma unroll
            for (int mi = 0; mi < 2; mi++)
                #pragma unroll
                for (int ni = 0; ni < 4; ni++)
                    mma_tf32(acc[mi][ni], a[mi], bf[ni]);
        }
        __syncthreads();
    }

    // Epilogue: + bias, float2 stores
    #pragma unroll
    for (int mi = 0; mi < 2; mi++) {
        const size_t r0 = brow + wm * 32 + mi * 16;
        #pragma unroll
        for (int ni = 0; ni < 4; ni++) {
            const int c0 = wn * 32 + ni * 8 + tig * 2;
            const float b0 = bias[c0], b1 = bias[c0 + 1];
            float2 v0 = make_float2(acc[mi][ni][0] + b0, acc[mi][ni][1] + b1);
            float2 v1 = make_float2(acc[mi][ni][2] + b0, acc[mi][ni][3] + b1);
            *reinterpret_cast<float2*>(emis + (r0 + g) * NLS + c0)     = v0;
            *reinterpret_cast<float2*>(emis + (r0 + 8 + g) * NLS + c0) = v1;
        }
    }
}

// ---------------------------------------------------------------------------
// Shared helper: max + exp over smem rows of width 64 (stride 68),
// 2 threads per row. Pair-exact shfl mask: the two lanes of a pair are always
// convergent (same r), so mask 3<<(lane&30) is legal at ANY nC (no deadlock).
// ---------------------------------------------------------------------------
__device__ __forceinline__ void maxexp_rows(float* buf, float* mrow, int t, int nC) {
    const int r = t >> 1, h = t & 1;
    const unsigned pm = 3u << ((t & 31) & 30);
    if (r < nC) {
        float* row = buf + r * 68 + h * 32;
        float m = row[0];
        #pragma unroll
        for (int k = 1; k < 32; k++) m = fmaxf(m, row[k]);
        m = fmaxf(m, __shfl_xor_sync(pm, m, 1));
        if (h == 0) mrow[r] = m;
        #pragma unroll
        for (int k = 0; k < 32; k++) row[k] = __expf(row[k] - m);
    }
}

// ---------------------------------------------------------------------------
// One FULL tree level (nP in {512,256,128,64}; every block has 32 parents).
// lt[p,l] = m[2p] + log( sum_k exp(left-m) * exp(trans[l,k]) )   via tf32 MMA
// new[p,l] = emis[node] + lt + rt
// ---------------------------------------------------------------------------
__global__ __launch_bounds__(128) void level_kernel(
    const float* __restrict__ child, size_t childStride,   // batch stride
    const float* __restrict__ trans,
    const float* __restrict__ emis, int nodeOff,
    float* __restrict__ out, size_t outStride)
{
    __shared__ float Ts[64][68];   // Ts[l][k] = exp(trans[l,k])
    __shared__ float Es[64][68];   // exp'd child rows; reused for S = m + log(sum)
    __shared__ float mrow[64];

    const int t   = threadIdx.x;
    const int wid = t >> 5, lane = t & 31;
    const int g   = lane >> 2, tig = lane & 3;
    const int b   = blockIdx.y;
    const int pbase = blockIdx.x * 32;

    // Child rows into smem (coalesced float4) — issue FIRST
    const float* cb = child + (size_t)b * childStride + (size_t)pbase * 2 * 64;
    #pragma unroll
    for (int i = 0; i < 8; i++) {
        int idx = t + 128 * i;       // float4 index 0..1023
        int r = idx >> 4, c4 = idx & 15;
        float4 v = *reinterpret_cast<const float4*>(cb + (size_t)r * 64 + c4 * 4);
        *reinterpret_cast<float4*>(&Es[r][c4 * 4]) = v;
    }

    // Prefetch emission rows for the combine step (in flight across syncs)
    float er[16];
    #pragma unroll
    for (int i = 0; i < 16; i++) {
        int idx = t + 128 * i;       // 0..2047
        int p = idx >> 6, l = idx & 63;
        er[i] = emis[((size_t)b * NTREE + nodeOff + pbase + p) * NLS + l];
    }

    // exp(trans) into smem
    #pragma unroll
    for (int i = 0; i < 32; i++) {
        int idx = t + 128 * i;
        Ts[idx >> 6][idx & 63] = __expf(trans[idx]);
    }
    __syncthreads();

    maxexp_rows(&Es[0][0], mrow, t, 64);
    __syncthreads();

    // S = E @ exp(trans)^T : warp w handles rows [16w, 16w+16), all 64 cols
    const int rm = wid * 16;
    float acc[8][4];
    #pragma unroll
    for (int ni = 0; ni < 8; ni++)
        #pragma unroll
        for (int j = 0; j < 4; j++) acc[ni][j] = 0.f;

    #pragma unroll
    for (int kk = 0; kk < 8; kk++) {
        const int k0 = kk * 8;
        uint32_t a[4];
        a[0] = f2tf32(Es[rm + g][k0 + tig]);
        a[1] = f2tf32(Es[rm + 8 + g][k0 + tig]);
        a[2] = f2tf32(Es[rm + g][k0 + tig + 4]);
        a[3] = f2tf32(Es[rm + 8 + g][k0 + tig + 4]);
        #pragma unroll
        for (int ni = 0; ni < 8; ni++) {
            uint32_t bf[2];
            bf[0] = f2tf32(Ts[ni * 8 + g][k0 + tig]);
            bf[1] = f2tf32(Ts[ni * 8 + g][k0 + tig + 4]);
            mma_tf32(acc[ni], a, bf);
        }
    }

    // Epilogue: S = m + log(sum); each warp overwrites ONLY its own E rows
    const float m0 = mrow[rm + g], m1 = mrow[rm + 8 + g];
    #pragma unroll
    for (int ni = 0; ni < 8; ni++) {
        const int c0 = ni * 8 + tig * 2;
        Es[rm + g][c0]         = m0 + __logf(acc[ni][0]);
        Es[rm + g][c0 + 1]     = m0 + __logf(acc[ni][1]);
        Es[rm + 8 + g][c0]     = m1 + __logf(acc[ni][2]);
        Es[rm + 8 + g][c0 + 1] = m1 + __logf(acc[ni][3]);
    }
    __syncthreads();

    // Combine: new[p,l] = emis[node] + S[2p][l] + S[2p+1][l]
    #pragma unroll
    for (int i = 0; i < 16; i++) {
        int idx = t + 128 * i;       // 0..2047
        int p = idx >> 6, l = idx & 63;
        out[(size_t)b * outStride + (size_t)(pbase + p) * 64 + l]
            = er[i] + Es[2 * p][l] + Es[2 * p + 1][l];
    }
}

// ---------------------------------------------------------------------------
// Fused tail: levels nP = 32,16,8,4,2,1. One block per batch element.
// Ping-pong smem buffers; S computed in place (row-independent MMA).
// ---------------------------------------------------------------------------
__global__ __launch_bounds__(128) void tail_kernel(
    const float* __restrict__ child, size_t childStride,
    const float* __restrict__ trans,
    const float* __restrict__ emis,
    float* __restrict__ out)
{
    __shared__ float Ts[64][68];
    __shared__ float B0[64][68];
    __shared__ float B1[32][68];
    __shared__ float mrow[64];

    const int t   = threadIdx.x;
    const int wid = t >> 5, lane = t & 31;
    const int g   = lane >> 2, tig = lane & 3;
    const int b   = blockIdx.x;

    // exp(trans)
    #pragma unroll
    for (int i = 0; i < 32; i++) {
        int idx = t + 128 * i;
        Ts[idx >> 6][idx & 63] = __expf(trans[idx]);
    }
    // 64 child rows (output of the nP=64 level)
    const float* cb = child + (size_t)b * childStride;
    #pragma unroll
    for (int i = 0; i < 8; i++) {
        int idx = t + 128 * i;
        int r = idx >> 4, c4 = idx & 15;
        float4 v = *reinterpret_cast<const float4*>(cb + (size_t)r * 64 + c4 * 4);
        *reinterpret_cast<float4*>(&B0[r][c4 * 4]) = v;
    }
    #pragma unroll
    for (int i = 0; i < 17; i++) {
        int idx = t + 128 * i;
        if (idx < 32 * 68) (&B1[0][0])[idx] = 0.f;
    }
    __syncthreads();

    float* cur = &B0[0][0];
    float* nxt = &B1[0][0];

    for (int nP = 32; nP >= 1; nP >>= 1) {
        const int nC = 2 * nP;

        maxexp_rows(cur, mrow, t, nC);
        __syncthreads();

        // MMA over rows [16w, 16w+16) for warps covering [0, nC)
        const int rm = wid * 16;
        if (rm < nC) {
            float acc[8][4];
            #pragma unroll
            for (int ni = 0; ni < 8; ni++)
                #pragma unroll
                for (int j = 0; j < 4; j++) acc[ni][j] = 0.f;

            #pragma unroll
            for (int kk = 0; kk < 8; kk++) {
                const int k0 = kk * 8;
                uint32_t a[4];
                a[0] = f2tf32(cur[(rm + g) * 68 + k0 + tig]);
                a[1] = f2tf32(cur[(rm + 8 + g) * 68 + k0 + tig]);
                a[2] = f2tf32(cur[(rm + g) * 68 + k0 + tig + 4]);
                a[3] = f2tf32(cur[(rm + 8 + g) * 68 + k0 + tig + 4]);
                #pragma unroll
                for (int ni = 0; ni < 8; ni++) {
                    uint32_t bf[2];
                    bf[0] = f2tf32(Ts[ni * 8 + g][k0 + tig]);
                    bf[1] = f2tf32(Ts[ni * 8 + g][k0 + tig + 4]);
                    mma_tf32(acc[ni], a, bf);
                }
            }
            const float m0 = mrow[rm + g], m1 = mrow[rm + 8 + g];
            #pragma unroll
            for (int ni = 0; ni < 8; ni++) {
                const int c0 = ni * 8 + tig * 2;
                cur[(rm + g) * 68 + c0]         = m0 + __logf(acc[ni][0]);
                cur[(rm + g) * 68 + c0 + 1]     = m0 + __logf(acc[ni][1]);
                cur[(rm + 8 + g) * 68 + c0]     = m1 + __logf(acc[ni][2]);
                cur[(rm + 8 + g) * 68 + c0 + 1] = m1 + __logf(acc[ni][3]);
            }
        }
        __syncthreads();

        // Combine into parents
        for (int i = t; i < nP * 64; i += 128) {
            int p = i >> 6, l = i & 63;
            float e = emis[((size_t)b * NTREE + (nP - 1) + p) * NLS + l];
            float v = e + cur[(2 * p) * 68 + l] + cur[(2 * p + 1) * 68 + l];
            if (nP == 1) out[(size_t)b * 64 + l] = v;
            else         nxt[p * 68 + l] = v;
        }
        __syncthreads();

        float* tmp = cur; cur = nxt; nxt = tmp;
    }
}

extern "C" void kernel_launch(void* const* d_in, const int* in_sizes, int n_in,
                              void* d_out, int out_size)
{
    const float* hidden = (const float*)d_in[0];
    const float* W      = (const float*)d_in[1];
    const float* bias   = (const float*)d_in[2];
    const float* trans  = (const float*)d_in[3];
    float* out = (float*)d_out;

    float *emis, *bufA, *bufB;
    cudaGetSymbolAddress((void**)&emis, g_emis);
    cudaGetSymbolAddress((void**)&bufA, g_bufA);
    cudaGetSymbolAddress((void**)&bufB, g_bufB);

    cudaFuncSetAttribute(emis_kernel,
                         cudaFuncAttributeMaxDynamicSharedMemorySize, EMIS_SMEM);
    emis_kernel<<<MROWS / 128, 256, EMIS_SMEM>>>(hidden, W, bias, emis);

    // Leaves live at emis rows [1023, 2047) of each batch element
    const float* child = emis + (size_t)1023 * 64;
    size_t childStride = (size_t)NTREE * 64;
    float* bufs[2] = {bufA, bufB};
    int cur = 0;

    for (int nP = 512; nP >= 64; nP >>= 1) {
        float* o = bufs[cur];
        size_t oStride = (size_t)512 * 64;
        dim3 grid(nP / 32, Bq);
        level_kernel<<<grid, 128>>>(child, childStride, trans, emis, nP - 1, o, oStride);
        child = o;
        childStride = oStride;
        cur ^= 1;
    }

    // Fused levels nP = 32 .. 1
    tail_kernel<<<Bq, 128>>>(child, childStride, trans, emis, out);
}

// round 7
// speedup vs baseline: 1.0244x; 1.0244x over previous
#include <cuda_runtime.h>
#include <cstdint>

#define Bq    128
#define NTREE 2047
#define DIN   512
#define NLS   64
#define MROWS (Bq * NTREE)
#define NKT   (DIN / 32)

// Scratch (no allocations allowed): emissions + level buffers.
__device__ float g_emis[(size_t)MROWS * NLS];        // 67 MB
__device__ float g_bufA[(size_t)Bq * 512 * NLS];     // 16.8 MB
__device__ float g_bufB[(size_t)Bq * 512 * NLS];     // 16.8 MB

// tf32 MMA reads only the tf32 bit-fields of the operand register; feeding raw
// fp32 bits == RZ truncation (measured: rel_err 2.9e-4, gate 1e-3).
__device__ __forceinline__ uint32_t f2tf32(float f) { return __float_as_uint(f); }

__device__ __forceinline__ void mma_tf32(float c[4], const uint32_t a[4], const uint32_t b[2]) {
    asm volatile(
        "mma.sync.aligned.m16n8k8.row.col.f32.tf32.tf32.f32 "
        "{%0,%1,%2,%3}, {%4,%5,%6,%7}, {%8,%9}, {%0,%1,%2,%3};"
        : "+f"(c[0]), "+f"(c[1]), "+f"(c[2]), "+f"(c[3])
        : "r"(a[0]), "r"(a[1]), "r"(a[2]), "r"(a[3]), "r"(b[0]), "r"(b[1]));
}

__device__ __forceinline__ void cp_async16(void* smem_dst, const void* gmem_src) {
    uint32_t dst = (uint32_t)__cvta_generic_to_shared(smem_dst);
    asm volatile("cp.async.cg.shared.global [%0], [%1], 16;"
                 :: "r"(dst), "l"(gmem_src) : "memory");
}
__device__ __forceinline__ void cp_commit() {
    asm volatile("cp.async.commit_group;" ::: "memory");
}
__device__ __forceinline__ void cp_wait1() {
    asm volatile("cp.async.wait_group 1;" ::: "memory");
}

// ---------------------------------------------------------------------------
// Emission GEMM: emis[M,64] = hidden[M,512] @ W[512,64] + b
// BM=128, BN=64, BK=32; 256 threads = 8 warps in 4(M) x 2(N); warp tile 32x32.
// 3-stage cp.async pipeline, dynamic smem (81 KB) -> 2 CTAs/SM.
// (Held fixed this round to isolate the tree-fusion delta.)
// ---------------------------------------------------------------------------
#define AS_STRIDE 36
#define BS_STRIDE 72
#define A_STAGE   (128 * AS_STRIDE)
#define B_STAGE   (32 * BS_STRIDE)
#define EMIS_SMEM ((3 * A_STAGE + 3 * B_STAGE) * 4)   // 82944 bytes

extern __shared__ float dynsm[];

__global__ __launch_bounds__(256) void emis_kernel(
    const float* __restrict__ hidden, const float* __restrict__ W,
    const float* __restrict__ bias, float* __restrict__ emis)
{
    const int t    = threadIdx.x;
    const int wid  = t >> 5, lane = t & 31;
    const int g    = lane >> 2, tig = lane & 3;
    const int wm   = wid & 3, wn = wid >> 2;
    const size_t brow = (size_t)blockIdx.x * 128;

    float* Abase = dynsm;
    float* Bbase = dynsm + 3 * A_STAGE;

    const int a_r0 = t >> 3, a_c4 = t & 7;
    const int b_r0 = t >> 4, b_c4 = t & 15;

    auto load_tiles = [&](int kt, int s) {
        const int kb = kt * 32;
        float* As = Abase + s * A_STAGE;
        float* Bs = Bbase + s * B_STAGE;
        #pragma unroll
        for (int i = 0; i < 4; i++) {
            int r = a_r0 + 32 * i;
            cp_async16(As + r * AS_STRIDE + a_c4 * 4,
                       hidden + (brow + r) * DIN + kb + a_c4 * 4);
        }
        #pragma unroll
        for (int i = 0; i < 2; i++) {
            int r = b_r0 + 16 * i;
            cp_async16(Bs + r * BS_STRIDE + b_c4 * 4,
                       W + (size_t)(kb + r) * NLS + b_c4 * 4);
        }
        cp_commit();
    };

    float acc[2][4][4];
    #pragma unroll
    for (int mi = 0; mi < 2; mi++)
        #pragma unroll
        for (int ni = 0; ni < 4; ni++)
            #pragma unroll
            for (int j = 0; j < 4; j++) acc[mi][ni][j] = 0.f;

    load_tiles(0, 0);
    load_tiles(1, 1);

    for (int kt = 0; kt < NKT; kt++) {
        cp_wait1();
        __syncthreads();
        if (kt + 2 < NKT) load_tiles(kt + 2, (kt + 2) % 3);
        else              cp_commit();   // keep group accounting exact

        const int s = kt % 3;
        const float* As = Abase + s * A_STAGE;
        const float* Bs = Bbase + s * B_STAGE;

        #pragma unroll
        for (int kk = 0; kk < 4; kk++) {
            const int k0 = kk * 8;
            uint32_t a[2][4];
            #pragma unroll
            for (int mi = 0; mi < 2; mi++) {
                int r0 = wm * 32 + mi * 16;
                a[mi][0] = f2tf32(As[(r0 + g) * AS_STRIDE + k0 + tig]);
                a[mi][1] = f2tf32(As[(r0 + 8 + g) * AS_STRIDE + k0 + tig]);
                a[mi][2] = f2tf32(As[(r0 + g) * AS_STRIDE + k0 + tig + 4]);
                a[mi][3] = f2tf32(As[(r0 + 8 + g) * AS_STRIDE + k0 + tig + 4]);
            }
            uint32_t bf[4][2];
            #pragma unroll
            for (int ni = 0; ni < 4; ni++) {
                int c0 = wn * 32 + ni * 8;
                bf[ni][0] = f2tf32(Bs[(k0 + tig) * BS_STRIDE + c0 + g]);
                bf[ni][1] = f2tf32(Bs[(k0 + tig + 4) * BS_STRIDE + c0 + g]);
            }
            #pragma unroll
            for (int mi = 0; mi < 2; mi++)
                #pragma unroll
                for (int ni = 0; ni < 4; ni++)
                    mma_tf32(acc[mi][ni], a[mi], bf[ni]);
        }
        __syncthreads();
    }

    #pragma unroll
    for (int mi = 0; mi < 2; mi++) {
        const size_t r0 = brow + wm * 32 + mi * 16;
        #pragma unroll
        for (int ni = 0; ni < 4; ni++) {
            const int c0 = wn * 32 + ni * 8 + tig * 2;
            const float b0 = bias[c0], b1 = bias[c0 + 1];
            float2 v0 = make_float2(acc[mi][ni][0] + b0, acc[mi][ni][1] + b1);
            float2 v1 = make_float2(acc[mi][ni][2] + b0, acc[mi][ni][3] + b1);
            *reinterpret_cast<float2*>(emis + (r0 + g) * NLS + c0)     = v0;
            *reinterpret_cast<float2*>(emis + (r0 + 8 + g) * NLS + c0) = v1;
        }
    }
}

// ---------------------------------------------------------------------------
// Fused DOUBLE level. Block = 32 top parents of one batch element
//   -> 64 mid children -> 128 grandchild rows (contiguous in heap layout).
// 256 threads = 8 warps. Dynamic smem: Ts[64][68] + Es[128][68] + mrow[128].
// Mid results stored in-place at EVEN Es rows (single-reader == writer).
// ---------------------------------------------------------------------------
#define F2_SMEM ((64 * 68 + 128 * 68 + 128) * 4)   // 52736 bytes

__global__ __launch_bounds__(256) void fused2_kernel(
    const float* __restrict__ child, size_t childStride,  // grandchild rows
    const float* __restrict__ trans,
    const float* __restrict__ emis, int midOff, int topOff,
    float* __restrict__ out, size_t outStride)
{
    float* Ts   = dynsm;                       // [64][68]
    float* Es   = dynsm + 64 * 68;             // [128][68]
    float* mrow = dynsm + 64 * 68 + 128 * 68;  // [128]

    const int t   = threadIdx.x;
    const int wid = t >> 5, lane = t & 31;
    const int g   = lane >> 2, tig = lane & 3;
    const unsigned pm = 3u << (lane & 30);
    const int b   = blockIdx.y;
    const int pbase = blockIdx.x * 32;

    // 128 grandchild rows into smem (float4, coalesced) — issue FIRST
    const float* cb = child + (size_t)b * childStride + (size_t)pbase * 4 * 64;
    #pragma unroll
    for (int i = 0; i < 8; i++) {
        int idx = t + 256 * i;            // float4 index 0..2047
        int r = idx >> 4, c4 = idx & 15;
        float4 v = *reinterpret_cast<const float4*>(cb + (size_t)r * 64 + c4 * 4);
        *reinterpret_cast<float4*>(&Es[r * 68 + c4 * 4]) = v;
    }

    // Prefetch emission rows for both combine steps (stay in flight)
    float em[16], et[8];
    #pragma unroll
    for (int i = 0; i < 16; i++) {
        int idx = t + 256 * i;            // 0..4095
        int p = idx >> 6, l = idx & 63;   // mid p in 0..63
        em[i] = emis[((size_t)b * NTREE + midOff + 2 * pbase + p) * NLS + l];
    }
    #pragma unroll
    for (int i = 0; i < 8; i++) {
        int idx = t + 256 * i;            // 0..2047
        int q = idx >> 6, l = idx & 63;   // top q in 0..31
        et[i] = emis[((size_t)b * NTREE + topOff + pbase + q) * NLS + l];
    }

    // exp(trans) into smem
    #pragma unroll
    for (int i = 0; i < 16; i++) {
        int idx = t + 256 * i;            // 0..4095
        Ts[(idx >> 6) * 68 + (idx & 63)] = __expf(trans[idx]);
    }
    __syncthreads();

    // ---- Level A: 128 child rows -> 64 mid rows ----
    {   // max + exp: 2 threads per row, 128 rows == 256 threads exactly
        const int r = t >> 1, h = t & 1;
        float* row = Es + r * 68 + h * 32;
        float m = row[0];
        #pragma unroll
        for (int k = 1; k < 32; k++) m = fmaxf(m, row[k]);
        m = fmaxf(m, __shfl_xor_sync(pm, m, 1));
        if (h == 0) mrow[r] = m;
        #pragma unroll
        for (int k = 0; k < 32; k++) row[k] = __expf(row[k] - m);
    }
    __syncthreads();

    {   // S = E @ exp(trans)^T : warp w -> rows [16w, 16w+16)
        const int rm = wid * 16;
        float acc[8][4];
        #pragma unroll
        for (int ni = 0; ni < 8; ni++)
            #pragma unroll
            for (int j = 0; j < 4; j++) acc[ni][j] = 0.f;

        #pragma unroll
        for (int kk = 0; kk < 8; kk++) {
            const int k0 = kk * 8;
            uint32_t a[4];
            a[0] = f2tf32(Es[(rm + g) * 68 + k0 + tig]);
            a[1] = f2tf32(Es[(rm + 8 + g) * 68 + k0 + tig]);
            a[2] = f2tf32(Es[(rm + g) * 68 + k0 + tig + 4]);
            a[3] = f2tf32(Es[(rm + 8 + g) * 68 + k0 + tig + 4]);
            #pragma unroll
            for (int ni = 0; ni < 8; ni++) {
                uint32_t bf[2];
                bf[0] = f2tf32(Ts[(ni * 8 + g) * 68 + k0 + tig]);
                bf[1] = f2tf32(Ts[(ni * 8 + g) * 68 + k0 + tig + 4]);
                mma_tf32(acc[ni], a, bf);
            }
        }
        const float m0 = mrow[rm + g], m1 = mrow[rm + 8 + g];
        #pragma unroll
        for (int ni = 0; ni < 8; ni++) {
            const int c0 = ni * 8 + tig * 2;
            Es[(rm + g) * 68 + c0]         = m0 + __logf(acc[ni][0]);
            Es[(rm + g) * 68 + c0 + 1]     = m0 + __logf(acc[ni][1]);
            Es[(rm + 8 + g) * 68 + c0]     = m1 + __logf(acc[ni][2]);
            Es[(rm + 8 + g) * 68 + c0 + 1] = m1 + __logf(acc[ni][3]);
        }
    }
    __syncthreads();

    // Combine mid: mid[p] = em + S[2p] + S[2p+1], stored IN-PLACE at row 2p.
    // Element (p,l): sole reader of S[2p][l]/S[2p+1][l] is its writer -> safe.
    #pragma unroll
    for (int i = 0; i < 16; i++) {
        int idx = t + 256 * i;
        int p = idx >> 6, l = idx & 63;
        float v = em[i] + Es[(2 * p) * 68 + l] + Es[(2 * p + 1) * 68 + l];
        Es[(2 * p) * 68 + l] = v;
    }
    __syncthreads();

    // ---- Level B: 64 mid rows (at even Es rows) -> 32 top rows ----
    if (t < 128) {   // max + exp on 64 rows, 2 threads per row
        const int r = t >> 1, h = t & 1;
        float* row = Es + (2 * r) * 68 + h * 32;
        float m = row[0];
        #pragma unroll
        for (int k = 1; k < 32; k++) m = fmaxf(m, row[k]);
        m = fmaxf(m, __shfl_xor_sync(pm, m, 1));
        if (h == 0) mrow[r] = m;
        #pragma unroll
        for (int k = 0; k < 32; k++) row[k] = __expf(row[k] - m);
    }
    __syncthreads();

    if (wid < 4) {   // warps 0..3 cover 64 mid rows
        const int rm = wid * 16;
        float acc[8][4];
        #pragma unroll
        for (int ni = 0; ni < 8; ni++)
            #pragma unroll
            for (int j = 0; j < 4; j++) acc[ni][j] = 0.f;

        #pragma unroll
        for (int kk = 0; kk < 8; kk++) {
            const int k0 = kk * 8;
            uint32_t a[4];
            a[0] = f2tf32(Es[(2 * (rm + g)) * 68 + k0 + tig]);
            a[1] = f2tf32(Es[(2 * (rm + 8 + g)) * 68 + k0 + tig]);
            a[2] = f2tf32(Es[(2 * (rm + g)) * 68 + k0 + tig + 4]);
            a[3] = f2tf32(Es[(2 * (rm + 8 + g)) * 68 + k0 + tig + 4]);
            #pragma unroll
            for (int ni = 0; ni < 8; ni++) {
                uint32_t bf[2];
                bf[0] = f2tf32(Ts[(ni * 8 + g) * 68 + k0 + tig]);
                bf[1] = f2tf32(Ts[(ni * 8 + g) * 68 + k0 + tig + 4]);
                mma_tf32(acc[ni], a, bf);
            }
        }
        const float m0 = mrow[rm + g], m1 = mrow[rm + 8 + g];
        #pragma unroll
        for (int ni = 0; ni < 8; ni++) {
            const int c0 = ni * 8 + tig * 2;
            Es[(2 * (rm + g)) * 68 + c0]         = m0 + __logf(acc[ni][0]);
            Es[(2 * (rm + g)) * 68 + c0 + 1]     = m0 + __logf(acc[ni][1]);
            Es[(2 * (rm + 8 + g)) * 68 + c0]     = m1 + __logf(acc[ni][2]);
            Es[(2 * (rm + 8 + g)) * 68 + c0 + 1] = m1 + __logf(acc[ni][3]);
        }
    }
    __syncthreads();

    // Combine top: top[q] = et + S2[mid 2q] + S2[mid 2q+1] = rows 4q, 4q+2.
    #pragma unroll
    for (int i = 0; i < 8; i++) {
        int idx = t + 256 * i;
        int q = idx >> 6, l = idx & 63;
        out[(size_t)b * outStride + (size_t)(pbase + q) * 64 + l]
            = et[i] + Es[(4 * q) * 68 + l] + Es[(4 * q + 2) * 68 + l];
    }
}

// ---------------------------------------------------------------------------
// Fused tail: levels nP = 32,16,8,4,2,1. One block per batch element.
// ---------------------------------------------------------------------------
__global__ __launch_bounds__(128) void tail_kernel(
    const float* __restrict__ child, size_t childStride,
    const float* __restrict__ trans,
    const float* __restrict__ emis,
    float* __restrict__ out)
{
    __shared__ float Ts[64][68];
    __shared__ float B0[64][68];
    __shared__ float B1[32][68];
    __shared__ float mrow[64];

    const int t   = threadIdx.x;
    const int wid = t >> 5, lane = t & 31;
    const int g   = lane >> 2, tig = lane & 3;
    const unsigned pm = 3u << (lane & 30);
    const int b   = blockIdx.x;

    #pragma unroll
    for (int i = 0; i < 32; i++) {
        int idx = t + 128 * i;
        Ts[idx >> 6][idx & 63] = __expf(trans[idx]);
    }
    const float* cb = child + (size_t)b * childStride;
    #pragma unroll
    for (int i = 0; i < 8; i++) {
        int idx = t + 128 * i;
        int r = idx >> 4, c4 = idx & 15;
        float4 v = *reinterpret_cast<const float4*>(cb + (size_t)r * 64 + c4 * 4);
        *reinterpret_cast<float4*>(&B0[r][c4 * 4]) = v;
    }
    #pragma unroll
    for (int i = 0; i < 17; i++) {
        int idx = t + 128 * i;
        if (idx < 32 * 68) (&B1[0][0])[idx] = 0.f;
    }
    __syncthreads();

    float* cur = &B0[0][0];
    float* nxt = &B1[0][0];

    for (int nP = 32; nP >= 1; nP >>= 1) {
        const int nC = 2 * nP;

        {   // max + exp, 2 threads/row, pair-exact mask (no deadlock at any nC)
            const int r = t >> 1, h = t & 1;
            if (r < nC) {
                float* row = cur + r * 68 + h * 32;
                float m = row[0];
                #pragma unroll
                for (int k = 1; k < 32; k++) m = fmaxf(m, row[k]);
                m = fmaxf(m, __shfl_xor_sync(pm, m, 1));
                if (h == 0) mrow[r] = m;
                #pragma unroll
                for (int k = 0; k < 32; k++) row[k] = __expf(row[k] - m);
            }
        }
        __syncthreads();

        const int rm = wid * 16;
        if (rm < nC) {
            float acc[8][4];
            #pragma unroll
            for (int ni = 0; ni < 8; ni++)
                #pragma unroll
                for (int j = 0; j < 4; j++) acc[ni][j] = 0.f;

            #pragma unroll
            for (int kk = 0; kk < 8; kk++) {
                const int k0 = kk * 8;
                uint32_t a[4];
                a[0] = f2tf32(cur[(rm + g) * 68 + k0 + tig]);
                a[1] = f2tf32(cur[(rm + 8 + g) * 68 + k0 + tig]);
                a[2] = f2tf32(cur[(rm + g) * 68 + k0 + tig + 4]);
                a[3] = f2tf32(cur[(rm + 8 + g) * 68 + k0 + tig + 4]);
                #pragma unroll
                for (int ni = 0; ni < 8; ni++) {
                    uint32_t bf[2];
                    bf[0] = f2tf32(Ts[ni * 8 + g][k0 + tig]);
                    bf[1] = f2tf32(Ts[ni * 8 + g][k0 + tig + 4]);
                    mma_tf32(acc[ni], a, bf);
                }
            }
            const float m0 = mrow[rm + g], m1 = mrow[rm + 8 + g];
            #pragma unroll
            for (int ni = 0; ni < 8; ni++) {
                const int c0 = ni * 8 + tig * 2;
                cur[(rm + g) * 68 + c0]         = m0 + __logf(acc[ni][0]);
                cur[(rm + g) * 68 + c0 + 1]     = m0 + __logf(acc[ni][1]);
                cur[(rm + 8 + g) * 68 + c0]     = m1 + __logf(acc[ni][2]);
                cur[(rm + 8 + g) * 68 + c0 + 1] = m1 + __logf(acc[ni][3]);
            }
        }
        __syncthreads();

        for (int i = t; i < nP * 64; i += 128) {
            int p = i >> 6, l = i & 63;
            float e = emis[((size_t)b * NTREE + (nP - 1) + p) * NLS + l];
            float v = e + cur[(2 * p) * 68 + l] + cur[(2 * p + 1) * 68 + l];
            if (nP == 1) out[(size_t)b * 64 + l] = v;
            else         nxt[p * 68 + l] = v;
        }
        __syncthreads();

        float* tmp = cur; cur = nxt; nxt = tmp;
    }
}

extern "C" void kernel_launch(void* const* d_in, const int* in_sizes, int n_in,
                              void* d_out, int out_size)
{
    const float* hidden = (const float*)d_in[0];
    const float* W      = (const float*)d_in[1];
    const float* bias   = (const float*)d_in[2];
    const float* trans  = (const float*)d_in[3];
    float* out = (float*)d_out;

    float *emis, *bufA, *bufB;
    cudaGetSymbolAddress((void**)&emis, g_emis);
    cudaGetSymbolAddress((void**)&bufA, g_bufA);
    cudaGetSymbolAddress((void**)&bufB, g_bufB);

    cudaFuncSetAttribute(emis_kernel,
                         cudaFuncAttributeMaxDynamicSharedMemorySize, EMIS_SMEM);
    cudaFuncSetAttribute(fused2_kernel,
                         cudaFuncAttributeMaxDynamicSharedMemorySize, F2_SMEM);

    emis_kernel<<<MROWS / 128, 256, EMIS_SMEM>>>(hidden, W, bias, emis);

    const size_t bufStride = (size_t)512 * 64;

    // Levels 512+256 fused: grandchildren = leaves (emis rows 1023..2046)
    {
        dim3 grid(8, Bq);   // 256 top parents / 32
        fused2_kernel<<<grid, 256, F2_SMEM>>>(
            emis + (size_t)1023 * 64, (size_t)NTREE * 64, trans,
            emis, 511, 255, bufA, bufStride);
    }
    // Levels 128+64 fused: grandchildren = 256-level buffer
    {
        dim3 grid(2, Bq);   // 64 top parents / 32
        fused2_kernel<<<grid, 256, F2_SMEM>>>(
            bufA, bufStride, trans,
            emis, 127, 63, bufB, bufStride);
    }
    // Fused levels nP = 32 .. 1
    tail_kernel<<<Bq, 128>>>(bufB, bufStride, trans, emis, out);
}

// round 13
// speedup vs baseline: 1.0464x; 1.0214x over previous
#include <cuda_runtime.h>
#include <cstdint>

#define Bq    128
#define NTREE 2047
#define DIN   512
#define NLS   64
#define MROWS (Bq * NTREE)
#define NKT   (DIN / 32)

__device__ float g_emis[(size_t)MROWS * NLS];        // 67 MB
__device__ float g_bufA[(size_t)Bq * 512 * NLS];     // 16.8 MB
__device__ float g_bufB[(size_t)Bq * 512 * NLS];     // 16.8 MB

// tf32 MMA reads only the tf32 bit-fields; raw fp32 bits == RZ truncation
// (measured rel_err 2.9e-4, gate 1e-3).
__device__ __forceinline__ uint32_t f2tf32(float f) { return __float_as_uint(f); }

__device__ __forceinline__ void mma_tf32(float c[4], const uint32_t a[4], const uint32_t b[2]) {
    asm volatile(
        "mma.sync.aligned.m16n8k8.row.col.f32.tf32.tf32.f32 "
        "{%0,%1,%2,%3}, {%4,%5,%6,%7}, {%8,%9}, {%0,%1,%2,%3};"
        : "+f"(c[0]), "+f"(c[1]), "+f"(c[2]), "+f"(c[3])
        : "r"(a[0]), "r"(a[1]), "r"(a[2]), "r"(a[3]), "r"(b[0]), "r"(b[1]));
}

__device__ __forceinline__ void cp_async16(void* smem_dst, const void* gmem_src) {
    uint32_t dst = (uint32_t)__cvta_generic_to_shared(smem_dst);
    asm volatile("cp.async.cg.shared.global [%0], [%1], 16;"
                 :: "r"(dst), "l"(gmem_src) : "memory");
}
__device__ __forceinline__ void cp_commit() {
    asm volatile("cp.async.commit_group;" ::: "memory");
}
__device__ __forceinline__ void cp_wait2() {
    asm volatile("cp.async.wait_group 2;" ::: "memory");
}
__device__ __forceinline__ void cp_wait0() {
    asm volatile("cp.async.wait_group 0;" ::: "memory");
}

// ---------------------------------------------------------------------------
// Emission GEMM: emis[M,64] = hidden[M,512] @ W[512,64] + b
// BM=128, BN=64, BK=32; 256 threads; 4-stage cp.async pipeline,
// ONE __syncthreads per k-iter. 110 KB dyn smem -> 2 CTAs/SM.
// ---------------------------------------------------------------------------
#define AS_STRIDE 36
#define BS_STRIDE 72
#define A_STAGE   (128 * AS_STRIDE)
#define B_STAGE   (32 * BS_STRIDE)
#define EMIS_SMEM ((4 * A_STAGE + 4 * B_STAGE) * 4)   // 110592 bytes

extern __shared__ float dynsm[];

__global__ __launch_bounds__(256) void emis_kernel(
    const float* __restrict__ hidden, const float* __restrict__ W,
    const float* __restrict__ bias, float* __restrict__ emis)
{
    const int t    = threadIdx.x;
    const int wid  = t >> 5, lane = t & 31;
    const int g    = lane >> 2, tig = lane & 3;
    const int wm   = wid & 3, wn = wid >> 2;
    const size_t brow = (size_t)blockIdx.x * 128;

    float* Abase = dynsm;
    float* Bbase = dynsm + 4 * A_STAGE;

    const int a_r0 = t >> 3, a_c4 = t & 7;
    const int b_r0 = t >> 4, b_c4 = t & 15;

    auto load_tiles = [&](int kt, int s) {
        const int kb = kt * 32;
        float* As = Abase + s * A_STAGE;
        float* Bs = Bbase + s * B_STAGE;
        #pragma unroll
        for (int i = 0; i < 4; i++) {
            int r = a_r0 + 32 * i;
            cp_async16(As + r * AS_STRIDE + a_c4 * 4,
                       hidden + (brow + r) * DIN + kb + a_c4 * 4);
        }
        #pragma unroll
        for (int i = 0; i < 2; i++) {
            int r = b_r0 + 16 * i;
            cp_async16(Bs + r * BS_STRIDE + b_c4 * 4,
                       W + (size_t)(kb + r) * NLS + b_c4 * 4);
        }
        cp_commit();
    };

    float acc[2][4][4];
    #pragma unroll
    for (int mi = 0; mi < 2; mi++)
        #pragma unroll
        for (int ni = 0; ni < 4; ni++)
            #pragma unroll
            for (int j = 0; j < 4; j++) acc[mi][ni][j] = 0.f;

    load_tiles(0, 0);
    load_tiles(1, 1);
    load_tiles(2, 2);

    for (int kt = 0; kt < NKT; kt++) {
        // Stage kt complete (<=2 newer groups pending), then one barrier.
        cp_wait2();
        __syncthreads();
        // Issue AFTER the sync: target stage (kt+3)%4 == (kt-1)%4, whose
        // readers (iter kt-1) all passed this sync. Hazard-free, 1 sync/iter.
        if (kt + 3 < NKT) load_tiles(kt + 3, (kt + 3) & 3);
        else              cp_commit();   // keep group accounting exact

        const int s = kt & 3;
        const float* As = Abase + s * A_STAGE;
        const float* Bs = Bbase + s * B_STAGE;

        #pragma unroll
        for (int kk = 0; kk < 4; kk++) {
            const int k0 = kk * 8;
            uint32_t a[2][4];
            #pragma unroll
            for (int mi = 0; mi < 2; mi++) {
                int r0 = wm * 32 + mi * 16;
                a[mi][0] = f2tf32(As[(r0 + g) * AS_STRIDE + k0 + tig]);
                a[mi][1] = f2tf32(As[(r0 + 8 + g) * AS_STRIDE + k0 + tig]);
                a[mi][2] = f2tf32(As[(r0 + g) * AS_STRIDE + k0 + tig + 4]);
                a[mi][3] = f2tf32(As[(r0 + 8 + g) * AS_STRIDE + k0 + tig + 4]);
            }
            uint32_t bf[4][2];
            #pragma unroll
            for (int ni = 0; ni < 4; ni++) {
                int c0 = wn * 32 + ni * 8;
                bf[ni][0] = f2tf32(Bs[(k0 + tig) * BS_STRIDE + c0 + g]);
                bf[ni][1] = f2tf32(Bs[(k0 + tig + 4) * BS_STRIDE + c0 + g]);
            }
            #pragma unroll
            for (int mi = 0; mi < 2; mi++)
                #pragma unroll
                for (int ni = 0; ni < 4; ni++)
                    mma_tf32(acc[mi][ni], a[mi], bf[ni]);
        }
    }

    #pragma unroll
    for (int mi = 0; mi < 2; mi++) {
        const size_t r0 = brow + wm * 32 + mi * 16;
        #pragma unroll
        for (int ni = 0; ni < 4; ni++) {
            const int c0 = wn * 32 + ni * 8 + tig * 2;
            const float b0 = bias[c0], b1 = bias[c0 + 1];
            float2 v0 = make_float2(acc[mi][ni][0] + b0, acc[mi][ni][1] + b1);
            float2 v1 = make_float2(acc[mi][ni][2] + b0, acc[mi][ni][3] + b1);
            *reinterpret_cast<float2*>(emis + (r0 + g) * NLS + c0)     = v0;
            *reinterpret_cast<float2*>(emis + (r0 + 8 + g) * NLS + c0) = v1;
        }
    }
}

// ---------------------------------------------------------------------------
// Fused DOUBLE level (unchanged — passed at R7).
// ---------------------------------------------------------------------------
#define F2_SMEM ((64 * 68 + 128 * 68 + 128) * 4)   // 52736 bytes

__global__ __launch_bounds__(256) void fused2_kernel(
    const float* __restrict__ child, size_t childStride,
    const float* __restrict__ trans,
    const float* __restrict__ emis, int midOff, int topOff,
    float* __restrict__ out, size_t outStride)
{
    float* Ts   = dynsm;
    float* Es   = dynsm + 64 * 68;
    float* mrow = dynsm + 64 * 68 + 128 * 68;

    const int t   = threadIdx.x;
    const int wid = t >> 5, lane = t & 31;
    const int g   = lane >> 2, tig = lane & 3;
    const unsigned pm = 3u << (lane & 30);
    const int b   = blockIdx.y;
    const int pbase = blockIdx.x * 32;

    const float* cb = child + (size_t)b * childStride + (size_t)pbase * 4 * 64;
    #pragma unroll
    for (int i = 0; i < 8; i++) {
        int idx = t + 256 * i;
        int r = idx >> 4, c4 = idx & 15;
        float4 v = *reinterpret_cast<const float4*>(cb + (size_t)r * 64 + c4 * 4);
        *reinterpret_cast<float4*>(&Es[r * 68 + c4 * 4]) = v;
    }

    float em[16], et[8];
    #pragma unroll
    for (int i = 0; i < 16; i++) {
        int idx = t + 256 * i;
        int p = idx >> 6, l = idx & 63;
        em[i] = emis[((size_t)b * NTREE + midOff + 2 * pbase + p) * NLS + l];
    }
    #pragma unroll
    for (int i = 0; i < 8; i++) {
        int idx = t + 256 * i;
        int q = idx >> 6, l = idx & 63;
        et[i] = emis[((size_t)b * NTREE + topOff + pbase + q) * NLS + l];
    }

    #pragma unroll
    for (int i = 0; i < 16; i++) {
        int idx = t + 256 * i;
        Ts[(idx >> 6) * 68 + (idx & 63)] = __expf(trans[idx]);
    }
    __syncthreads();

    {   // Level A maxexp: 2 threads/row x 128 rows
        const int r = t >> 1, h = t & 1;
        float* row = Es + r * 68 + h * 32;
        float m = row[0];
        #pragma unroll
        for (int k = 1; k < 32; k++) m = fmaxf(m, row[k]);
        m = fmaxf(m, __shfl_xor_sync(pm, m, 1));
        if (h == 0) mrow[r] = m;
        #pragma unroll
        for (int k = 0; k < 32; k++) row[k] = __expf(row[k] - m);
    }
    __syncthreads();

    {   // Level A MMA
        const int rm = wid * 16;
        float acc[8][4];
        #pragma unroll
        for (int ni = 0; ni < 8; ni++)
            #pragma unroll
            for (int j = 0; j < 4; j++) acc[ni][j] = 0.f;

        #pragma unroll
        for (int kk = 0; kk < 8; kk++) {
            const int k0 = kk * 8;
            uint32_t a[4];
            a[0] = f2tf32(Es[(rm + g) * 68 + k0 + tig]);
            a[1] = f2tf32(Es[(rm + 8 + g) * 68 + k0 + tig]);
            a[2] = f2tf32(Es[(rm + g) * 68 + k0 + tig + 4]);
            a[3] = f2tf32(Es[(rm + 8 + g) * 68 + k0 + tig + 4]);
            #pragma unroll
            for (int ni = 0; ni < 8; ni++) {
                uint32_t bf[2];
                bf[0] = f2tf32(Ts[(ni * 8 + g) * 68 + k0 + tig]);
                bf[1] = f2tf32(Ts[(ni * 8 + g) * 68 + k0 + tig + 4]);
                mma_tf32(acc[ni], a, bf);
            }
        }
        const float m0 = mrow[rm + g], m1 = mrow[rm + 8 + g];
        #pragma unroll
        for (int ni = 0; ni < 8; ni++) {
            const int c0 = ni * 8 + tig * 2;
            Es[(rm + g) * 68 + c0]         = m0 + __logf(acc[ni][0]);
            Es[(rm + g) * 68 + c0 + 1]     = m0 + __logf(acc[ni][1]);
            Es[(rm + 8 + g) * 68 + c0]     = m1 + __logf(acc[ni][2]);
            Es[(rm + 8 + g) * 68 + c0 + 1] = m1 + __logf(acc[ni][3]);
        }
    }
    __syncthreads();

    #pragma unroll
    for (int i = 0; i < 16; i++) {
        int idx = t + 256 * i;
        int p = idx >> 6, l = idx & 63;
        float v = em[i] + Es[(2 * p) * 68 + l] + Es[(2 * p + 1) * 68 + l];
        Es[(2 * p) * 68 + l] = v;
    }
    __syncthreads();

    if (t < 128) {
        const int r = t >> 1, h = t & 1;
        float* row = Es + (2 * r) * 68 + h * 32;
        float m = row[0];
        #pragma unroll
        for (int k = 1; k < 32; k++) m = fmaxf(m, row[k]);
        m = fmaxf(m, __shfl_xor_sync(pm, m, 1));
        if (h == 0) mrow[r] = m;
        #pragma unroll
        for (int k = 0; k < 32; k++) row[k] = __expf(row[k] - m);
    }
    __syncthreads();

    if (wid < 4) {
        const int rm = wid * 16;
        float acc[8][4];
        #pragma unroll
        for (int ni = 0; ni < 8; ni++)
            #pragma unroll
            for (int j = 0; j < 4; j++) acc[ni][j] = 0.f;

        #pragma unroll
        for (int kk = 0; kk < 8; kk++) {
            const int k0 = kk * 8;
            uint32_t a[4];
            a[0] = f2tf32(Es[(2 * (rm + g)) * 68 + k0 + tig]);
            a[1] = f2tf32(Es[(2 * (rm + 8 + g)) * 68 + k0 + tig]);
            a[2] = f2tf32(Es[(2 * (rm + g)) * 68 + k0 + tig + 4]);
            a[3] = f2tf32(Es[(2 * (rm + 8 + g)) * 68 + k0 + tig + 4]);
            #pragma unroll
            for (int ni = 0; ni < 8; ni++) {
                uint32_t bf[2];
                bf[0] = f2tf32(Ts[(ni * 8 + g) * 68 + k0 + tig]);
                bf[1] = f2tf32(Ts[(ni * 8 + g) * 68 + k0 + tig + 4]);
                mma_tf32(acc[ni], a, bf);
            }
        }
        const float m0 = mrow[rm + g], m1 = mrow[rm + 8 + g];
        #pragma unroll
        for (int ni = 0; ni < 8; ni++) {
            const int c0 = ni * 8 + tig * 2;
            Es[(2 * (rm + g)) * 68 + c0]         = m0 + __logf(acc[ni][0]);
            Es[(2 * (rm + g)) * 68 + c0 + 1]     = m0 + __logf(acc[ni][1]);
            Es[(2 * (rm + 8 + g)) * 68 + c0]     = m1 + __logf(acc[ni][2]);
            Es[(2 * (rm + 8 + g)) * 68 + c0 + 1] = m1 + __logf(acc[ni][3]);
        }
    }
    __syncthreads();

    #pragma unroll
    for (int i = 0; i < 8; i++) {
        int idx = t + 256 * i;
        int q = idx >> 6, l = idx & 63;
        out[(size_t)b * outStride + (size_t)(pbase + q) * 64 + l]
            = et[i] + Es[(4 * q) * 68 + l] + Es[(4 * q + 2) * 68 + l];
    }
}

// ---------------------------------------------------------------------------
// Fused tail (nP=32..1): 256 threads; emis rows 0..62 + child tile prefetched
// via cp.async; maxexp 4 threads/row; MMA 4(M) x 2(N) over all 8 warps.
// ---------------------------------------------------------------------------
#define TAIL_SMEM ((64*68 + 64*68 + 32*68 + 63*64 + 64) * 4)   // 59904 bytes

__global__ __launch_bounds__(256) void tail_kernel(
    const float* __restrict__ child, size_t childStride,
    const float* __restrict__ trans,
    const float* __restrict__ emis,
    float* __restrict__ out)
{
    float* Ts   = dynsm;                 // [64][68]
    float* B0   = Ts + 64 * 68;          // [64][68]
    float* B1   = B0 + 64 * 68;          // [32][68]
    float* ES   = B1 + 32 * 68;          // [63][64] emis rows 0..62
    float* mrow = ES + 63 * 64;          // [64]

    const int t   = threadIdx.x;
    const int wid = t >> 5, lane = t & 31;
    const int g   = lane >> 2, tig = lane & 3;
    const int wm  = wid & 3, wn = wid >> 2;
    const unsigned qmask = 0xFu << (lane & 28);
    const int b   = blockIdx.x;

    // Prefetch all emis node rows 0..62 (1008 float4) via cp.async
    const float* eb = emis + (size_t)b * NTREE * 64;
    for (int i = t; i < 1008; i += 256)
        cp_async16(ES + i * 4, eb + i * 4);
    // Prefetch 64 child rows into B0 (row stride 68 floats = 272 B, 16B-aligned)
    const float* cb = child + (size_t)b * childStride;
    #pragma unroll
    for (int i = 0; i < 4; i++) {
        int idx = t + 256 * i;
        int r = idx >> 4, c4 = idx & 15;
        cp_async16(B0 + r * 68 + c4 * 4, cb + (size_t)r * 64 + c4 * 4);
    }
    cp_commit();

    // Overlap: exp(trans) + zero B1 while cp.async is in flight
    #pragma unroll
    for (int i = 0; i < 16; i++) {
        int idx = t + 256 * i;
        Ts[(idx >> 6) * 68 + (idx & 63)] = __expf(trans[idx]);
    }
    for (int i = t; i < 32 * 68; i += 256) B1[i] = 0.f;

    cp_wait0();
    __syncthreads();

    float* cur = B0;
    float* nxt = B1;

    for (int nP = 32; nP >= 1; nP >>= 1) {
        const int nC = 2 * nP;

        {   // max + exp: 4 threads/row (quarters + 2 shfls), quad-exact mask
            const int r = t >> 2, h = t & 3;
            if (r < nC) {
                float* row = cur + r * 68 + h * 16;
                float m = row[0];
                #pragma unroll
                for (int k = 1; k < 16; k++) m = fmaxf(m, row[k]);
                m = fmaxf(m, __shfl_xor_sync(qmask, m, 1));
                m = fmaxf(m, __shfl_xor_sync(qmask, m, 2));
                if (h == 0) mrow[r] = m;
                #pragma unroll
                for (int k = 0; k < 16; k++) row[k] = __expf(row[k] - m);
            }
        }
        __syncthreads();

        // MMA: warp (wm, wn) -> rows [16wm,16wm+16), cols [32wn,32wn+32)
        const int rm = wm * 16;
        if (rm < nC) {
            float acc[4][4];
            #pragma unroll
            for (int ni = 0; ni < 4; ni++)
                #pragma unroll
                for (int j = 0; j < 4; j++) acc[ni][j] = 0.f;

            #pragma unroll
            for (int kk = 0; kk < 8; kk++) {
                const int k0 = kk * 8;
                uint32_t a[4];
                a[0] = f2tf32(cur[(rm + g) * 68 + k0 + tig]);
                a[1] = f2tf32(cur[(rm + 8 + g) * 68 + k0 + tig]);
                a[2] = f2tf32(cur[(rm + g) * 68 + k0 + tig + 4]);
                a[3] = f2tf32(cur[(rm + 8 + g) * 68 + k0 + tig + 4]);
                #pragma unroll
                for (int ni = 0; ni < 4; ni++) {
                    const int nrow = wn * 32 + ni * 8 + g;
                    uint32_t bf[2];
                    bf[0] = f2tf32(Ts[nrow * 68 + k0 + tig]);
                    bf[1] = f2tf32(Ts[nrow * 68 + k0 + tig + 4]);
                    mma_tf32(acc[ni], a, bf);
                }
            }
            const float m0 = mrow[rm + g], m1 = mrow[rm + 8 + g];
            #pragma unroll
            for (int ni = 0; ni < 4; ni++) {
                const int c0 = wn * 32 + ni * 8 + tig * 2;
                cur[(rm + g) * 68 + c0]         = m0 + __logf(acc[ni][0]);
                cur[(rm + g) * 68 + c0 + 1]     = m0 + __logf(acc[ni][1]);
                cur[(rm + 8 + g) * 68 + c0]     = m1 + __logf(acc[ni][2]);
                cur[(rm + 8 + g) * 68 + c0 + 1] = m1 + __logf(acc[ni][3]);
            }
        }
        __syncthreads();

        // Combine into parents (emis from smem: zero global traffic)
        for (int i = t; i < nP * 64; i += 256) {
            int p = i >> 6, l = i & 63;
            float v = ES[(nP - 1 + p) * 64 + l]
                    + cur[(2 * p) * 68 + l] + cur[(2 * p + 1) * 68 + l];
            if (nP == 1) out[(size_t)b * 64 + l] = v;
            else         nxt[p * 68 + l] = v;
        }
        __syncthreads();

        float* tmp = cur; cur = nxt; nxt = tmp;
    }
}

extern "C" void kernel_launch(void* const* d_in, const int* in_sizes, int n_in,
                              void* d_out, int out_size)
{
    const float* hidden = (const float*)d_in[0];
    const float* W      = (const float*)d_in[1];
    const float* bias   = (const float*)d_in[2];
    const float* trans  = (const float*)d_in[3];
    float* out = (float*)d_out;

    float *emis, *bufA, *bufB;
    cudaGetSymbolAddress((void**)&emis, g_emis);
    cudaGetSymbolAddress((void**)&bufA, g_bufA);
    cudaGetSymbolAddress((void**)&bufB, g_bufB);

    cudaFuncSetAttribute(emis_kernel,
                         cudaFuncAttributeMaxDynamicSharedMemorySize, EMIS_SMEM);
    cudaFuncSetAttribute(fused2_kernel,
                         cudaFuncAttributeMaxDynamicSharedMemorySize, F2_SMEM);
    cudaFuncSetAttribute(tail_kernel,
                         cudaFuncAttributeMaxDynamicSharedMemorySize, TAIL_SMEM);

    emis_kernel<<<MROWS / 128, 256, EMIS_SMEM>>>(hidden, W, bias, emis);

    const size_t bufStride = (size_t)512 * 64;

    {   // Levels 512+256 fused (grandchildren = leaves)
        dim3 grid(8, Bq);
        fused2_kernel<<<grid, 256, F2_SMEM>>>(
            emis + (size_t)1023 * 64, (size_t)NTREE * 64, trans,
            emis, 511, 255, bufA, bufStride);
    }
    {   // Levels 128+64 fused
        dim3 grid(2, Bq);
        fused2_kernel<<<grid, 256, F2_SMEM>>>(
            bufA, bufStride, trans,
            emis, 127, 63, bufB, bufStride);
    }
    // Levels 32..1
    tail_kernel<<<Bq, 256, TAIL_SMEM>>>(bufB, bufStride, trans, emis, out);
}